// round 1
// baseline (speedup 1.0000x reference)
#include <cuda_runtime.h>
#include <cuda_bf16.h>
#include <math.h>

// ---------------------------------------------------------------------------
// Problem constants
// ---------------------------------------------------------------------------
#define Bq      2
#define Sq      2048
#define Dq      2048
#define NH      16
#define NKV     4
#define HD      128
#define QKV_O   3072            // (16 + 2*4) * 128
#define MROWS   (Bq * Sq)       // 4096

// GEMM tiling
#define BM 128
#define BN 128
#define BK 16
#define TM 8
#define TN 8
#define NTHREADS 256

#define NEG_INF_F (-1e9f)

// ---------------------------------------------------------------------------
// Static scratch (allocation-free rule: __device__ globals)
// ---------------------------------------------------------------------------
__device__ float g_qkv[(size_t)MROWS * QKV_O];                  // 50.3 MB
__device__ float g_q  [(size_t)Bq * NH  * Sq * HD];             // 33.5 MB
__device__ float g_k  [(size_t)Bq * NKV * Sq * HD];             //  8.4 MB
__device__ float g_v  [(size_t)Bq * NKV * Sq * HD];             //  8.4 MB
__device__ float g_vt [(size_t)Bq * NKV * HD * Sq];             //  8.4 MB  (V^T)
__device__ float g_sc [(size_t)Bq * NH  * Sq * Sq];             // 537  MB  (scores/probs)
__device__ float g_o  [(size_t)MROWS * Dq];                     // 33.5 MB  (attn out, [b,s,h*hd])

// ---------------------------------------------------------------------------
// Core NT GEMM tile:  C_tile(BMxBN) += A(BMxK, K-major) * B(BNxK, K-major)^T
// A points at the tile's first row, B at the tile's first row.
// kCount must be a multiple of BK; BM/BN rows must be fully in-bounds.
// ---------------------------------------------------------------------------
__device__ __forceinline__ void mm_tile(const float* __restrict__ A, int lda,
                                        const float* __restrict__ B, int ldb,
                                        int kCount, float (&acc)[TM][TN])
{
    __shared__ float As[BK][BM];
    __shared__ float Bs[BK][BN];

    const int tid = threadIdx.x;
    const int tr  = tid >> 4;   // 0..15
    const int tc  = tid & 15;   // 0..15

    for (int k0 = 0; k0 < kCount; k0 += BK) {
#pragma unroll
        for (int t = 0; t < 2; t++) {
            int f   = tid + t * NTHREADS;   // 0..511
            int row = f >> 2;               // 0..127
            int c4  = (f & 3) << 2;         // 0,4,8,12
            float4 va = *reinterpret_cast<const float4*>(A + (size_t)row * lda + k0 + c4);
            As[c4 + 0][row] = va.x;
            As[c4 + 1][row] = va.y;
            As[c4 + 2][row] = va.z;
            As[c4 + 3][row] = va.w;
            float4 vb = *reinterpret_cast<const float4*>(B + (size_t)row * ldb + k0 + c4);
            Bs[c4 + 0][row] = vb.x;
            Bs[c4 + 1][row] = vb.y;
            Bs[c4 + 2][row] = vb.z;
            Bs[c4 + 3][row] = vb.w;
        }
        __syncthreads();

#pragma unroll
        for (int kk = 0; kk < BK; kk++) {
            float a[TM], b[TN];
#pragma unroll
            for (int i = 0; i < TM; i += 4)
                *reinterpret_cast<float4*>(&a[i]) =
                    *reinterpret_cast<const float4*>(&As[kk][tr * TM + i]);
#pragma unroll
            for (int j = 0; j < TN; j += 4)
                *reinterpret_cast<float4*>(&b[j]) =
                    *reinterpret_cast<const float4*>(&Bs[kk][tc * TN + j]);
#pragma unroll
            for (int i = 0; i < TM; i++)
#pragma unroll
                for (int j = 0; j < TN; j++)
                    acc[i][j] = fmaf(a[i], b[j], acc[i][j]);
        }
        __syncthreads();
    }
}

// ---------------------------------------------------------------------------
// 1) QKV projection: g_qkv[4096,3072] = x[4096,2048] * w_qkv[3072,2048]^T
// ---------------------------------------------------------------------------
__global__ void k_gemm_qkv(const float* __restrict__ x, const float* __restrict__ w)
{
    const int m0 = blockIdx.y * BM;
    const int n0 = blockIdx.x * BN;
    float acc[TM][TN] = {};
    mm_tile(x + (size_t)m0 * Dq, Dq, w + (size_t)n0 * Dq, Dq, Dq, acc);

    const int tr = threadIdx.x >> 4, tc = threadIdx.x & 15;
#pragma unroll
    for (int i = 0; i < TM; i++) {
        float* dst = g_qkv + (size_t)(m0 + tr * TM + i) * QKV_O + n0 + tc * TN;
        *reinterpret_cast<float4*>(dst)     = make_float4(acc[i][0], acc[i][1], acc[i][2], acc[i][3]);
        *reinterpret_cast<float4*>(dst + 4) = make_float4(acc[i][4], acc[i][5], acc[i][6], acc[i][7]);
    }
}

// ---------------------------------------------------------------------------
// 2) RoPE + scatter into Q[b,h,s,d], K[b,hk,s,d], V[b,hk,s,d]
//    one block per (s, b)
// ---------------------------------------------------------------------------
__global__ void k_rope()
{
    const int s = blockIdx.x;
    const int b = blockIdx.y;
    const float* row = g_qkv + ((size_t)b * Sq + s) * QKV_O;

    __shared__ float cs[HD / 2], sn[HD / 2];
    const int tid = threadIdx.x;
    if (tid < HD / 2) {
        double invf = pow(10000.0, -((double)(2 * tid) / (double)HD));
        double ang  = (double)s * invf;
        cs[tid] = (float)cos(ang);
        sn[tid] = (float)sin(ang);
    }
    __syncthreads();

    // Q: 16 heads * 64 pairs
    for (int p = tid; p < NH * (HD / 2); p += NTHREADS) {
        int h = p >> 6, i = p & 63;
        float v0 = row[h * HD + 2 * i];
        float v1 = row[h * HD + 2 * i + 1];
        float* qd = g_q + ((size_t)(b * NH + h) * Sq + s) * HD;
        qd[2 * i]     = v0 * cs[i] - v1 * sn[i];
        qd[2 * i + 1] = v0 * sn[i] + v1 * cs[i];
    }
    // K: 4 heads * 64 pairs
    for (int p = tid; p < NKV * (HD / 2); p += NTHREADS) {
        int h = p >> 6, i = p & 63;
        float v0 = row[NH * HD + h * HD + 2 * i];
        float v1 = row[NH * HD + h * HD + 2 * i + 1];
        float* kd = g_k + ((size_t)(b * NKV + h) * Sq + s) * HD;
        kd[2 * i]     = v0 * cs[i] - v1 * sn[i];
        kd[2 * i + 1] = v0 * sn[i] + v1 * cs[i];
    }
    // V copy
    for (int p = tid; p < NKV * HD; p += NTHREADS) {
        int h = p >> 7, d = p & 127;
        g_v[((size_t)(b * NKV + h) * Sq + s) * HD + d] = row[(NH + NKV) * HD + p];
    }
}

// ---------------------------------------------------------------------------
// 3) V transpose: g_vt[bk, d, s] = g_v[bk, s, d]   (bk = b*NKV + hk, 8 total)
// ---------------------------------------------------------------------------
__global__ void k_transpose_v()
{
    __shared__ float tile[32][33];
    const int bk = blockIdx.z;
    const int d0 = blockIdx.x * 32;
    const int s0 = blockIdx.y * 32;
    const float* src = g_v  + (size_t)bk * Sq * HD;
    float*       dst = g_vt + (size_t)bk * Sq * HD;
    const int tx = threadIdx.x, ty = threadIdx.y;   // 32 x 8
    for (int yy = ty; yy < 32; yy += 8)
        tile[yy][tx] = src[(size_t)(s0 + yy) * HD + d0 + tx];
    __syncthreads();
    for (int yy = ty; yy < 32; yy += 8)
        dst[(size_t)(d0 + yy) * Sq + s0 + tx] = tile[tx][yy];
}

// ---------------------------------------------------------------------------
// 4) Scores: per (b,h), S = scale * Q K^T, lower-tri tiles only, mask diagonal
//    grid: (j_tile=16, i_tile=16, bh=32); blocks with j>i exit immediately
// ---------------------------------------------------------------------------
__global__ void k_scores()
{
    const int jt = blockIdx.x, it = blockIdx.y, bh = blockIdx.z;
    if (jt > it) return;
    const int b = bh >> 4, h = bh & 15, hk = h >> 2;

    const float* Qb = g_q + ((size_t)(b * NH + h) * Sq + (size_t)it * BM) * HD;
    const float* Kb = g_k + ((size_t)(b * NKV + hk) * Sq + (size_t)jt * BN) * HD;

    float acc[TM][TN] = {};
    mm_tile(Qb, HD, Kb, HD, HD, acc);

    float* Cb = g_sc + (size_t)bh * Sq * Sq;
    const float scale = 0.08838834764831845f;   // 128^-0.5
    const int tr = threadIdx.x >> 4, tc = threadIdx.x & 15;
#pragma unroll
    for (int i = 0; i < TM; i++) {
        const int m = it * BM + tr * TM + i;
#pragma unroll
        for (int j = 0; j < TN; j++) {
            const int n = jt * BN + tc * TN + j;
            Cb[(size_t)m * Sq + n] = (n <= m) ? acc[i][j] * scale : NEG_INF_F;
        }
    }
}

// ---------------------------------------------------------------------------
// 5) Row softmax, in place, over [0, round_up(i+1, 128))
//    one block (128 threads) per row; 65536 rows
// ---------------------------------------------------------------------------
__global__ void k_softmax()
{
    const size_t row = blockIdx.x;
    const int i = (int)(row & (Sq - 1));
    float* r = g_sc + row * Sq;
    const int limit = ((i >> 7) + 1) << 7;   // diagonal-tile boundary
    const int tid = threadIdx.x;

    float vals[16];
    int n = 0;
    float mx = -3.4e38f;
    for (int j = tid; j < limit; j += 128) {
        float v = r[j];
        vals[n++] = v;
        mx = fmaxf(mx, v);
    }
#pragma unroll
    for (int o = 16; o; o >>= 1) mx = fmaxf(mx, __shfl_xor_sync(0xFFFFFFFFu, mx, o));
    __shared__ float redm[4];
    if ((tid & 31) == 0) redm[tid >> 5] = mx;
    __syncthreads();
    mx = fmaxf(fmaxf(redm[0], redm[1]), fmaxf(redm[2], redm[3]));

    float sum = 0.f;
    for (int t = 0; t < n; t++) { vals[t] = __expf(vals[t] - mx); sum += vals[t]; }
#pragma unroll
    for (int o = 16; o; o >>= 1) sum += __shfl_xor_sync(0xFFFFFFFFu, sum, o);
    __shared__ float reds[4];
    if ((tid & 31) == 0) reds[tid >> 5] = sum;
    __syncthreads();
    sum = reds[0] + reds[1] + reds[2] + reds[3];

    const float inv = 1.0f / sum;
    n = 0;
    for (int j = tid; j < limit; j += 128) r[j] = vals[n++] * inv;
}

// ---------------------------------------------------------------------------
// 6) AV: per (b,h), O_tile = P[it*128.., :klim] * Vt^T ; write to g_o[b,s,h*hd+d]
//    grid: (1, i_tile=16, bh=32)
// ---------------------------------------------------------------------------
__global__ void k_av()
{
    const int it = blockIdx.y, bh = blockIdx.z;
    const int b = bh >> 4, h = bh & 15, hk = h >> 2;

    const float* Pb = g_sc + (size_t)bh * Sq * Sq + (size_t)it * BM * Sq;
    const float* Vb = g_vt + (size_t)(b * NKV + hk) * HD * Sq;   // [d, s], ld = Sq
    const int klim = (it + 1) * BM;                              // causal K truncation

    float acc[TM][TN] = {};
    mm_tile(Pb, Sq, Vb, Sq, klim, acc);

    const int tr = threadIdx.x >> 4, tc = threadIdx.x & 15;
#pragma unroll
    for (int i = 0; i < TM; i++) {
        const int s = it * BM + tr * TM + i;
        float* dst = g_o + ((size_t)b * Sq + s) * Dq + h * HD + tc * TN;
        *reinterpret_cast<float4*>(dst)     = make_float4(acc[i][0], acc[i][1], acc[i][2], acc[i][3]);
        *reinterpret_cast<float4*>(dst + 4) = make_float4(acc[i][4], acc[i][5], acc[i][6], acc[i][7]);
    }
}

// ---------------------------------------------------------------------------
// 7) Output projection: out[4096,2048] = g_o[4096,2048] * w_o[2048,2048]^T
// ---------------------------------------------------------------------------
__global__ void k_gemm_out(const float* __restrict__ wo, float* __restrict__ out)
{
    const int m0 = blockIdx.y * BM;
    const int n0 = blockIdx.x * BN;
    float acc[TM][TN] = {};
    mm_tile(g_o + (size_t)m0 * Dq, Dq, wo + (size_t)n0 * Dq, Dq, Dq, acc);

    const int tr = threadIdx.x >> 4, tc = threadIdx.x & 15;
#pragma unroll
    for (int i = 0; i < TM; i++) {
        float* dst = out + (size_t)(m0 + tr * TM + i) * Dq + n0 + tc * TN;
        *reinterpret_cast<float4*>(dst)     = make_float4(acc[i][0], acc[i][1], acc[i][2], acc[i][3]);
        *reinterpret_cast<float4*>(dst + 4) = make_float4(acc[i][4], acc[i][5], acc[i][6], acc[i][7]);
    }
}

// ---------------------------------------------------------------------------
// Launch
// ---------------------------------------------------------------------------
extern "C" void kernel_launch(void* const* d_in, const int* in_sizes, int n_in,
                              void* d_out, int out_size)
{
    const float* x     = (const float*)d_in[0];   // [2,2048,2048]
    const float* w_qkv = (const float*)d_in[1];   // [3072,2048]
    const float* w_o   = (const float*)d_in[2];   // [2048,2048]
    float* out = (float*)d_out;                   // [2,2048,2048]

    k_gemm_qkv<<<dim3(QKV_O / BN, MROWS / BM), NTHREADS>>>(x, w_qkv);
    k_rope<<<dim3(Sq, Bq), NTHREADS>>>();
    k_transpose_v<<<dim3(HD / 32, Sq / 32, Bq * NKV), dim3(32, 8)>>>();
    k_scores<<<dim3(Sq / BN, Sq / BM, Bq * NH), NTHREADS>>>();
    k_softmax<<<(unsigned)(Bq * NH * Sq), 128>>>();
    k_av<<<dim3(1, Sq / BM, Bq * NH), NTHREADS>>>();
    k_gemm_out<<<dim3(Dq / BN, MROWS / BM), NTHREADS>>>(w_o, out);
}

// round 3
// speedup vs baseline: 2.1609x; 2.1609x over previous
#include <cuda_runtime.h>
#include <cuda_bf16.h>
#include <math.h>
#include <cstdint>

// ---------------------------------------------------------------------------
// Problem constants
// ---------------------------------------------------------------------------
#define Bq      2
#define Sq      2048
#define Dq      2048
#define NH      16
#define NKV     4
#define HD      128
#define QKV_O   3072
#define MROWS   (Bq * Sq)
#define NEG_INF_F (-1e9f)

// GEMM tiling (tensor core, mma.sync m16n8k8 tf32)
#define BM 128
#define BN 128
#define BK 16
#define NTHREADS 256
#define SPAD 8

// ---------------------------------------------------------------------------
// Static scratch
// ---------------------------------------------------------------------------
__device__ float g_qkv[(size_t)MROWS * QKV_O];
__device__ float g_q  [(size_t)Bq * NH  * Sq * HD];
__device__ float g_k  [(size_t)Bq * NKV * Sq * HD];
__device__ float g_v  [(size_t)Bq * NKV * Sq * HD];
__device__ float g_vt [(size_t)Bq * NKV * HD * Sq];
__device__ float g_sc [(size_t)Bq * NH  * Sq * Sq];
__device__ float g_o  [(size_t)MROWS * Dq];

// ---------------------------------------------------------------------------
// Helpers
// ---------------------------------------------------------------------------
__device__ __forceinline__ uint32_t f2tf32(float x) {
    uint32_t r;
    asm("cvt.rna.tf32.f32 %0, %1;" : "=r"(r) : "f"(x));
    return r;
}

__device__ __forceinline__ void mma_tf32(float (&d)[4], const uint32_t (&a)[4],
                                         const uint32_t (&b)[2]) {
    asm volatile(
        "mma.sync.aligned.m16n8k8.row.col.f32.tf32.tf32.f32 "
        "{%0,%1,%2,%3}, {%4,%5,%6,%7}, {%8,%9}, {%0,%1,%2,%3};"
        : "+f"(d[0]), "+f"(d[1]), "+f"(d[2]), "+f"(d[3])
        : "r"(a[0]), "r"(a[1]), "r"(a[2]), "r"(a[3]), "r"(b[0]), "r"(b[1]));
}

// ---------------------------------------------------------------------------
// Core NT GEMM tile via tensor cores:
//   C(BMxBN) += A[128,K](K-major) * B[128,K](K-major)^T
// 8 warps: warp (wm=wid>>1 in 0..3, wn=wid&1 in 0..1); warp tile 32(M) x 64(N)
// acc[mi][ni][4]: mma m16n8k8 fragments. kCount multiple of BK.
// ---------------------------------------------------------------------------
__device__ __forceinline__ void mm_tile(const float* __restrict__ A, int lda,
                                        const float* __restrict__ B, int ldb,
                                        int kCount, float (&acc)[2][8][4])
{
    __shared__ uint32_t As[BK][BM + SPAD];
    __shared__ uint32_t Bs[BK][BN + SPAD];

    const int tid  = threadIdx.x;
    const int lane = tid & 31;
    const int wid  = tid >> 5;
    const int wm   = wid >> 1;          // 0..3
    const int wn   = wid & 1;           // 0..1
    const int r    = lane >> 2;         // 0..7
    const int c    = lane & 3;          // 0..3

    for (int k0 = 0; k0 < kCount; k0 += BK) {
#pragma unroll
        for (int t = 0; t < 2; t++) {
            int f   = tid + t * NTHREADS;   // 0..511
            int row = f >> 2;               // 0..127
            int c4  = (f & 3) << 2;         // 0,4,8,12
            float4 va = *reinterpret_cast<const float4*>(A + (size_t)row * lda + k0 + c4);
            As[c4 + 0][row] = f2tf32(va.x);
            As[c4 + 1][row] = f2tf32(va.y);
            As[c4 + 2][row] = f2tf32(va.z);
            As[c4 + 3][row] = f2tf32(va.w);
            float4 vb = *reinterpret_cast<const float4*>(B + (size_t)row * ldb + k0 + c4);
            Bs[c4 + 0][row] = f2tf32(vb.x);
            Bs[c4 + 1][row] = f2tf32(vb.y);
            Bs[c4 + 2][row] = f2tf32(vb.z);
            Bs[c4 + 3][row] = f2tf32(vb.w);
        }
        __syncthreads();

#pragma unroll
        for (int ks = 0; ks < BK; ks += 8) {
            uint32_t a[2][4];
#pragma unroll
            for (int mi = 0; mi < 2; mi++) {
                int m = wm * 32 + mi * 16 + r;
                a[mi][0] = As[ks + c][m];
                a[mi][1] = As[ks + c][m + 8];
                a[mi][2] = As[ks + c + 4][m];
                a[mi][3] = As[ks + c + 4][m + 8];
            }
            uint32_t b[8][2];
#pragma unroll
            for (int ni = 0; ni < 8; ni++) {
                int n = wn * 64 + ni * 8 + r;
                b[ni][0] = Bs[ks + c][n];
                b[ni][1] = Bs[ks + c + 4][n];
            }
#pragma unroll
            for (int mi = 0; mi < 2; mi++)
#pragma unroll
                for (int ni = 0; ni < 8; ni++)
                    mma_tf32(acc[mi][ni], a[mi], b[ni]);
        }
        __syncthreads();
    }
}

// Fragment owner coordinates (local to the 128x128 tile):
//   rows:  wm*32 + mi*16 + r   and  +8
//   cols:  wn*64 + ni*8 + 2c   and  +1

// ---------------------------------------------------------------------------
// 1) QKV projection: g_qkv = x * w_qkv^T
// ---------------------------------------------------------------------------
__global__ void __launch_bounds__(NTHREADS) k_gemm_qkv(const float* __restrict__ x,
                                                       const float* __restrict__ w)
{
    const int m0 = blockIdx.y * BM, n0 = blockIdx.x * BN;
    float acc[2][8][4] = {};
    mm_tile(x + (size_t)m0 * Dq, Dq, w + (size_t)n0 * Dq, Dq, Dq, acc);

    const int lane = threadIdx.x & 31, wid = threadIdx.x >> 5;
    const int wm = wid >> 1, wn = wid & 1, r = lane >> 2, c = lane & 3;
#pragma unroll
    for (int mi = 0; mi < 2; mi++) {
        const int m = m0 + wm * 32 + mi * 16 + r;
#pragma unroll
        for (int ni = 0; ni < 8; ni++) {
            const int n = n0 + wn * 64 + ni * 8 + 2 * c;
            *reinterpret_cast<float2*>(g_qkv + (size_t)m * QKV_O + n) =
                make_float2(acc[mi][ni][0], acc[mi][ni][1]);
            *reinterpret_cast<float2*>(g_qkv + (size_t)(m + 8) * QKV_O + n) =
                make_float2(acc[mi][ni][2], acc[mi][ni][3]);
        }
    }
}

// ---------------------------------------------------------------------------
// 2) RoPE + scatter
// ---------------------------------------------------------------------------
__global__ void k_rope()
{
    const int s = blockIdx.x, b = blockIdx.y;
    const float* row = g_qkv + ((size_t)b * Sq + s) * QKV_O;
    __shared__ float cs[HD / 2], sn[HD / 2];
    const int tid = threadIdx.x;
    if (tid < HD / 2) {
        double invf = pow(10000.0, -((double)(2 * tid) / (double)HD));
        double ang  = (double)s * invf;
        cs[tid] = (float)cos(ang);
        sn[tid] = (float)sin(ang);
    }
    __syncthreads();
    for (int p = tid; p < NH * (HD / 2); p += 256) {
        int h = p >> 6, i = p & 63;
        float v0 = row[h * HD + 2 * i], v1 = row[h * HD + 2 * i + 1];
        float* qd = g_q + ((size_t)(b * NH + h) * Sq + s) * HD;
        qd[2 * i]     = v0 * cs[i] - v1 * sn[i];
        qd[2 * i + 1] = v0 * sn[i] + v1 * cs[i];
    }
    for (int p = tid; p < NKV * (HD / 2); p += 256) {
        int h = p >> 6, i = p & 63;
        float v0 = row[NH * HD + h * HD + 2 * i], v1 = row[NH * HD + h * HD + 2 * i + 1];
        float* kd = g_k + ((size_t)(b * NKV + h) * Sq + s) * HD;
        kd[2 * i]     = v0 * cs[i] - v1 * sn[i];
        kd[2 * i + 1] = v0 * sn[i] + v1 * cs[i];
    }
    for (int p = tid; p < NKV * HD; p += 256) {
        int h = p >> 7, d = p & 127;
        g_v[((size_t)(b * NKV + h) * Sq + s) * HD + d] = row[(NH + NKV) * HD + p];
    }
}

// ---------------------------------------------------------------------------
// 3) V transpose
// ---------------------------------------------------------------------------
__global__ void k_transpose_v()
{
    __shared__ float tile[32][33];
    const int bk = blockIdx.z, d0 = blockIdx.x * 32, s0 = blockIdx.y * 32;
    const float* src = g_v  + (size_t)bk * Sq * HD;
    float*       dst = g_vt + (size_t)bk * Sq * HD;
    const int tx = threadIdx.x, ty = threadIdx.y;
    for (int yy = ty; yy < 32; yy += 8)
        tile[yy][tx] = src[(size_t)(s0 + yy) * HD + d0 + tx];
    __syncthreads();
    for (int yy = ty; yy < 32; yy += 8)
        dst[(size_t)(d0 + yy) * Sq + s0 + tx] = tile[tx][yy];
}

// ---------------------------------------------------------------------------
// 4) Scores: lower-tri tiles only, diag masked
// ---------------------------------------------------------------------------
__global__ void __launch_bounds__(NTHREADS) k_scores()
{
    const int jt = blockIdx.x, it = blockIdx.y, bh = blockIdx.z;
    if (jt > it) return;
    const int b = bh >> 4, h = bh & 15, hk = h >> 2;

    const float* Qb = g_q + ((size_t)(b * NH + h) * Sq + (size_t)it * BM) * HD;
    const float* Kb = g_k + ((size_t)(b * NKV + hk) * Sq + (size_t)jt * BN) * HD;

    float acc[2][8][4] = {};
    mm_tile(Qb, HD, Kb, HD, HD, acc);

    float* Cb = g_sc + (size_t)bh * Sq * Sq;
    const float scale = 0.08838834764831845f;
    const int lane = threadIdx.x & 31, wid = threadIdx.x >> 5;
    const int wm = wid >> 1, wn = wid & 1, r = lane >> 2, c = lane & 3;
#pragma unroll
    for (int mi = 0; mi < 2; mi++) {
        const int mrow[2] = { it * BM + wm * 32 + mi * 16 + r,
                              it * BM + wm * 32 + mi * 16 + r + 8 };
#pragma unroll
        for (int ni = 0; ni < 8; ni++) {
            const int n = jt * BN + wn * 64 + ni * 8 + 2 * c;
#pragma unroll
            for (int hrow = 0; hrow < 2; hrow++) {
                const int m = mrow[hrow];
                float v0 = acc[mi][ni][2 * hrow]     * scale;
                float v1 = acc[mi][ni][2 * hrow + 1] * scale;
                if (it == jt) {
                    if (n     > m) v0 = NEG_INF_F;
                    if (n + 1 > m) v1 = NEG_INF_F;
                }
                *reinterpret_cast<float2*>(Cb + (size_t)m * Sq + n) = make_float2(v0, v1);
            }
        }
    }
}

// ---------------------------------------------------------------------------
// 5) Row softmax in place over [0, round_up(i+1,128))
// ---------------------------------------------------------------------------
__global__ void k_softmax()
{
    const size_t row = blockIdx.x;
    const int i = (int)(row & (Sq - 1));
    float* r = g_sc + row * Sq;
    const int limit = ((i >> 7) + 1) << 7;
    const int tid = threadIdx.x;

    float vals[16];
    int n = 0;
    float mx = -3.4e38f;
    for (int j = tid; j < limit; j += 128) {
        float v = r[j];
        vals[n++] = v;
        mx = fmaxf(mx, v);
    }
#pragma unroll
    for (int o = 16; o; o >>= 1) mx = fmaxf(mx, __shfl_xor_sync(0xFFFFFFFFu, mx, o));
    __shared__ float redm[4];
    if ((tid & 31) == 0) redm[tid >> 5] = mx;
    __syncthreads();
    mx = fmaxf(fmaxf(redm[0], redm[1]), fmaxf(redm[2], redm[3]));

    float sum = 0.f;
    for (int t = 0; t < n; t++) { vals[t] = __expf(vals[t] - mx); sum += vals[t]; }
#pragma unroll
    for (int o = 16; o; o >>= 1) sum += __shfl_xor_sync(0xFFFFFFFFu, sum, o);
    __shared__ float reds[4];
    if ((tid & 31) == 0) reds[tid >> 5] = sum;
    __syncthreads();
    sum = reds[0] + reds[1] + reds[2] + reds[3];

    const float inv = 1.0f / sum;
    n = 0;
    for (int j = tid; j < limit; j += 128) r[j] = vals[n++] * inv;
}

// ---------------------------------------------------------------------------
// 6) AV -> g_o[b,s,h*hd+d]
// ---------------------------------------------------------------------------
__global__ void __launch_bounds__(NTHREADS) k_av()
{
    const int it = blockIdx.y, bh = blockIdx.z;
    const int b = bh >> 4, h = bh & 15, hk = h >> 2;

    const float* Pb = g_sc + (size_t)bh * Sq * Sq + (size_t)it * BM * Sq;
    const float* Vb = g_vt + (size_t)(b * NKV + hk) * HD * Sq;
    const int klim = (it + 1) * BM;

    float acc[2][8][4] = {};
    mm_tile(Pb, Sq, Vb, Sq, klim, acc);

    const int lane = threadIdx.x & 31, wid = threadIdx.x >> 5;
    const int wm = wid >> 1, wn = wid & 1, r = lane >> 2, c = lane & 3;
#pragma unroll
    for (int mi = 0; mi < 2; mi++) {
        const int s = it * BM + wm * 32 + mi * 16 + r;
#pragma unroll
        for (int ni = 0; ni < 8; ni++) {
            const int n = wn * 64 + ni * 8 + 2 * c;
            *reinterpret_cast<float2*>(g_o + ((size_t)b * Sq + s) * Dq + h * HD + n) =
                make_float2(acc[mi][ni][0], acc[mi][ni][1]);
            *reinterpret_cast<float2*>(g_o + ((size_t)b * Sq + s + 8) * Dq + h * HD + n) =
                make_float2(acc[mi][ni][2], acc[mi][ni][3]);
        }
    }
}

// ---------------------------------------------------------------------------
// 7) Output projection
// ---------------------------------------------------------------------------
__global__ void __launch_bounds__(NTHREADS) k_gemm_out(const float* __restrict__ wo,
                                                       float* __restrict__ out)
{
    const int m0 = blockIdx.y * BM, n0 = blockIdx.x * BN;
    float acc[2][8][4] = {};
    mm_tile(g_o + (size_t)m0 * Dq, Dq, wo + (size_t)n0 * Dq, Dq, Dq, acc);

    const int lane = threadIdx.x & 31, wid = threadIdx.x >> 5;
    const int wm = wid >> 1, wn = wid & 1, r = lane >> 2, c = lane & 3;
#pragma unroll
    for (int mi = 0; mi < 2; mi++) {
        const int m = m0 + wm * 32 + mi * 16 + r;
#pragma unroll
        for (int ni = 0; ni < 8; ni++) {
            const int n = n0 + wn * 64 + ni * 8 + 2 * c;
            *reinterpret_cast<float2*>(out + (size_t)m * Dq + n) =
                make_float2(acc[mi][ni][0], acc[mi][ni][1]);
            *reinterpret_cast<float2*>(out + (size_t)(m + 8) * Dq + n) =
                make_float2(acc[mi][ni][2], acc[mi][ni][3]);
        }
    }
}

// ---------------------------------------------------------------------------
// Launch
// ---------------------------------------------------------------------------
extern "C" void kernel_launch(void* const* d_in, const int* in_sizes, int n_in,
                              void* d_out, int out_size)
{
    const float* x     = (const float*)d_in[0];
    const float* w_qkv = (const float*)d_in[1];
    const float* w_o   = (const float*)d_in[2];
    float* out = (float*)d_out;

    k_gemm_qkv<<<dim3(QKV_O / BN, MROWS / BM), NTHREADS>>>(x, w_qkv);
    k_rope<<<dim3(Sq, Bq), 256>>>();
    k_transpose_v<<<dim3(HD / 32, Sq / 32, Bq * NKV), dim3(32, 8)>>>();
    k_scores<<<dim3(Sq / BN, Sq / BM, Bq * NH), NTHREADS>>>();
    k_softmax<<<(unsigned)(Bq * NH * Sq), 128>>>();
    k_av<<<dim3(1, Sq / BM, Bq * NH), NTHREADS>>>();
    k_gemm_out<<<dim3(Dq / BN, MROWS / BM), NTHREADS>>>(w_o, out);
}

// round 4
// speedup vs baseline: 2.7401x; 1.2681x over previous
#include <cuda_runtime.h>
#include <cuda_bf16.h>
#include <math.h>
#include <cstdint>

// ---------------------------------------------------------------------------
// Problem constants
// ---------------------------------------------------------------------------
#define Bq      2
#define Sq      2048
#define Dq      2048
#define NH      16
#define NKV     4
#define HD      128
#define QKV_O   3072
#define MROWS   (Bq * Sq)
#define NEG_INF_F (-1e9f)

// Projection GEMM tiling (mma.sync m16n8k8 tf32)
#define BM 128
#define BN 128
#define BK 16
#define NTHREADS 256
#define SPAD 8

// Flash kernel smem stride (128 + 8 pad)
#define TW 136
#define FLASH_SMEM (3 * 128 * TW * 4)

// ---------------------------------------------------------------------------
// Static scratch
// ---------------------------------------------------------------------------
__device__ float g_qkv[(size_t)MROWS * QKV_O];
__device__ float g_qt [(size_t)Bq * NH  * HD * Sq];   // Q transposed: [bh][d][s]
__device__ float g_kt [(size_t)Bq * NKV * HD * Sq];   // K transposed: [bk][d][s]
__device__ float g_v  [(size_t)Bq * NKV * Sq * HD];   // V natural:    [bk][s][d]
__device__ float g_o  [(size_t)MROWS * Dq];           // attn out [b,s,h*hd]

// ---------------------------------------------------------------------------
// Helpers
// ---------------------------------------------------------------------------
__device__ __forceinline__ uint32_t f2tf32(float x) {
    uint32_t r;
    asm("cvt.rna.tf32.f32 %0, %1;" : "=r"(r) : "f"(x));
    return r;
}

__device__ __forceinline__ void mma_tf32(float (&d)[4], const uint32_t (&a)[4],
                                         const uint32_t (&b)[2]) {
    asm volatile(
        "mma.sync.aligned.m16n8k8.row.col.f32.tf32.tf32.f32 "
        "{%0,%1,%2,%3}, {%4,%5,%6,%7}, {%8,%9}, {%0,%1,%2,%3};"
        : "+f"(d[0]), "+f"(d[1]), "+f"(d[2]), "+f"(d[3])
        : "r"(a[0]), "r"(a[1]), "r"(a[2]), "r"(a[3]), "r"(b[0]), "r"(b[1]));
}

// ---------------------------------------------------------------------------
// Projection NT GEMM tile (reg-prefetch double buffered):
//   C(128x128) += A[128,K](K-major) * B[128,K](K-major)^T
// 8 warps in 4(M)x2(N); warp tile 32x64.
// ---------------------------------------------------------------------------
__device__ __forceinline__ void mm_tile(const float* __restrict__ A, int lda,
                                        const float* __restrict__ B, int ldb,
                                        int kCount, float (&acc)[2][8][4])
{
    __shared__ uint32_t As[BK][BM + SPAD];
    __shared__ uint32_t Bs[BK][BN + SPAD];

    const int tid  = threadIdx.x;
    const int lane = tid & 31;
    const int wid  = tid >> 5;
    const int wm   = wid >> 1;
    const int wn   = wid & 1;
    const int r    = lane >> 2;
    const int c    = lane & 3;

    const int f0 = tid,        row0 = f0 >> 2, c40 = (f0 & 3) << 2;
    const int f1 = tid + 256,  row1 = f1 >> 2, c41 = (f1 & 3) << 2;

    float4 pa0 = *reinterpret_cast<const float4*>(A + (size_t)row0 * lda + c40);
    float4 pa1 = *reinterpret_cast<const float4*>(A + (size_t)row1 * lda + c41);
    float4 pb0 = *reinterpret_cast<const float4*>(B + (size_t)row0 * ldb + c40);
    float4 pb1 = *reinterpret_cast<const float4*>(B + (size_t)row1 * ldb + c41);

    for (int k0 = 0; k0 < kCount; k0 += BK) {
        As[c40 + 0][row0] = f2tf32(pa0.x); As[c40 + 1][row0] = f2tf32(pa0.y);
        As[c40 + 2][row0] = f2tf32(pa0.z); As[c40 + 3][row0] = f2tf32(pa0.w);
        As[c41 + 0][row1] = f2tf32(pa1.x); As[c41 + 1][row1] = f2tf32(pa1.y);
        As[c41 + 2][row1] = f2tf32(pa1.z); As[c41 + 3][row1] = f2tf32(pa1.w);
        Bs[c40 + 0][row0] = f2tf32(pb0.x); Bs[c40 + 1][row0] = f2tf32(pb0.y);
        Bs[c40 + 2][row0] = f2tf32(pb0.z); Bs[c40 + 3][row0] = f2tf32(pb0.w);
        Bs[c41 + 0][row1] = f2tf32(pb1.x); Bs[c41 + 1][row1] = f2tf32(pb1.y);
        Bs[c41 + 2][row1] = f2tf32(pb1.z); Bs[c41 + 3][row1] = f2tf32(pb1.w);
        __syncthreads();

        const int kn = k0 + BK;
        if (kn < kCount) {
            pa0 = *reinterpret_cast<const float4*>(A + (size_t)row0 * lda + kn + c40);
            pa1 = *reinterpret_cast<const float4*>(A + (size_t)row1 * lda + kn + c41);
            pb0 = *reinterpret_cast<const float4*>(B + (size_t)row0 * ldb + kn + c40);
            pb1 = *reinterpret_cast<const float4*>(B + (size_t)row1 * ldb + kn + c41);
        }

#pragma unroll
        for (int ks = 0; ks < BK; ks += 8) {
            uint32_t a[2][4];
#pragma unroll
            for (int mi = 0; mi < 2; mi++) {
                int m = wm * 32 + mi * 16 + r;
                a[mi][0] = As[ks + c][m];
                a[mi][1] = As[ks + c][m + 8];
                a[mi][2] = As[ks + c + 4][m];
                a[mi][3] = As[ks + c + 4][m + 8];
            }
#pragma unroll
            for (int ni = 0; ni < 8; ni++) {
                int n = wn * 64 + ni * 8 + r;
                uint32_t bb[2] = { Bs[ks + c][n], Bs[ks + c + 4][n] };
#pragma unroll
                for (int mi = 0; mi < 2; mi++)
                    mma_tf32(acc[mi][ni], a[mi], bb);
            }
        }
        __syncthreads();
    }
}

// ---------------------------------------------------------------------------
// 1) QKV projection
// ---------------------------------------------------------------------------
__global__ void __launch_bounds__(NTHREADS) k_gemm_qkv(const float* __restrict__ x,
                                                       const float* __restrict__ w)
{
    const int m0 = blockIdx.y * BM, n0 = blockIdx.x * BN;
    float acc[2][8][4] = {};
    mm_tile(x + (size_t)m0 * Dq, Dq, w + (size_t)n0 * Dq, Dq, Dq, acc);

    const int lane = threadIdx.x & 31, wid = threadIdx.x >> 5;
    const int wm = wid >> 1, wn = wid & 1, r = lane >> 2, c = lane & 3;
#pragma unroll
    for (int mi = 0; mi < 2; mi++) {
        const int m = m0 + wm * 32 + mi * 16 + r;
#pragma unroll
        for (int ni = 0; ni < 8; ni++) {
            const int n = n0 + wn * 64 + ni * 8 + 2 * c;
            *reinterpret_cast<float2*>(g_qkv + (size_t)m * QKV_O + n) =
                make_float2(acc[mi][ni][0], acc[mi][ni][1]);
            *reinterpret_cast<float2*>(g_qkv + (size_t)(m + 8) * QKV_O + n) =
                make_float2(acc[mi][ni][2], acc[mi][ni][3]);
        }
    }
}

// ---------------------------------------------------------------------------
// 2) RoPE + scatter (Q,K transposed [d][s]; V natural)
// ---------------------------------------------------------------------------
__global__ void k_rope()
{
    const int s = blockIdx.x, b = blockIdx.y;
    const float* row = g_qkv + ((size_t)b * Sq + s) * QKV_O;
    __shared__ float cs[HD / 2], sn[HD / 2];
    const int tid = threadIdx.x;
    if (tid < HD / 2) {
        double invf = pow(10000.0, -((double)(2 * tid) / (double)HD));
        double ang  = (double)s * invf;
        cs[tid] = (float)cos(ang);
        sn[tid] = (float)sin(ang);
    }
    __syncthreads();
    for (int p = tid; p < NH * (HD / 2); p += 256) {
        int h = p >> 6, i = p & 63;
        float v0 = row[h * HD + 2 * i], v1 = row[h * HD + 2 * i + 1];
        float* qd = g_qt + ((size_t)(b * NH + h) * HD + 2 * i) * Sq;
        qd[s]      = v0 * cs[i] - v1 * sn[i];
        qd[Sq + s] = v0 * sn[i] + v1 * cs[i];
    }
    for (int p = tid; p < NKV * (HD / 2); p += 256) {
        int h = p >> 6, i = p & 63;
        float v0 = row[NH * HD + h * HD + 2 * i], v1 = row[NH * HD + h * HD + 2 * i + 1];
        float* kd = g_kt + ((size_t)(b * NKV + h) * HD + 2 * i) * Sq;
        kd[s]      = v0 * cs[i] - v1 * sn[i];
        kd[Sq + s] = v0 * sn[i] + v1 * cs[i];
    }
    for (int p = tid; p < NKV * HD; p += 256) {
        int h = p >> 7, d = p & 127;
        g_v[((size_t)(b * NKV + h) * Sq + s) * HD + d] = row[(NH + NKV) * HD + p];
    }
}

// ---------------------------------------------------------------------------
// 3) Fused flash attention: per CTA one (bh, it). 8 warps, warp tile 16x128.
//    Qs [d][m], Ps [j][m], KVs [k][n] — all stride TW=136, tf32 in smem.
// ---------------------------------------------------------------------------
__global__ void __launch_bounds__(NTHREADS, 1) k_flash()
{
    extern __shared__ uint32_t sm[];
    uint32_t* Qs  = sm;
    uint32_t* Ps  = sm + 128 * TW;
    uint32_t* KVs = sm + 2 * 128 * TW;

    const int it = 15 - blockIdx.x;           // heavy tiles first
    const int bh = blockIdx.y;
    const int b = bh >> 4, h = bh & 15, hk = h >> 2;
    const int tid = threadIdx.x, lane = tid & 31, w = tid >> 5;
    const int r = lane >> 2, c = lane & 3;
    const int m0 = w * 16 + r;                // local Q row (and +8)

    // Load Q tile from transposed layout: Qs[d][m]
    const float* Qt = g_qt + (size_t)bh * HD * Sq + (size_t)it * 128;
#pragma unroll
    for (int i = 0; i < 16; i++) {
        int f = tid + i * 256;
        int k = f >> 5, m4 = (f & 31) << 2;
        float4 v = *reinterpret_cast<const float4*>(Qt + (size_t)k * Sq + m4);
        *reinterpret_cast<uint4*>(&Qs[k * TW + m4]) =
            make_uint4(f2tf32(v.x), f2tf32(v.y), f2tf32(v.z), f2tf32(v.w));
    }

    float acc_o[16][4] = {};
    float mprev0 = -1e30f, mprev1 = -1e30f;
    float l0 = 0.f, l1 = 0.f;
    const float scale = 0.08838834764831845f;

    const float* KtB = g_kt + (size_t)(b * NKV + hk) * HD * Sq;
    const float* VB  = g_v  + (size_t)(b * NKV + hk) * Sq * HD;

    for (int jt = 0; jt <= it; jt++) {
        __syncthreads();   // prev AV gemm done with KVs (and Q stores on iter 0)

        // Load K tile (transposed layout): KVs[d][n]
#pragma unroll
        for (int i = 0; i < 16; i++) {
            int f = tid + i * 256;
            int k = f >> 5, n4 = (f & 31) << 2;
            float4 v = *reinterpret_cast<const float4*>(
                KtB + (size_t)k * Sq + (size_t)jt * 128 + n4);
            *reinterpret_cast<uint4*>(&KVs[k * TW + n4]) =
                make_uint4(f2tf32(v.x), f2tf32(v.y), f2tf32(v.z), f2tf32(v.w));
        }
        __syncthreads();

        // S = Q K^T  (k over hd=128)
        float acc_s[16][4] = {};
#pragma unroll 2
        for (int kc = 0; kc < 128; kc += 8) {
            uint32_t a[4];
            const uint32_t* q0 = &Qs[(kc + c) * TW];
            const uint32_t* q1 = &Qs[(kc + c + 4) * TW];
            a[0] = q0[m0]; a[1] = q0[m0 + 8]; a[2] = q1[m0]; a[3] = q1[m0 + 8];
            const uint32_t* b0p = &KVs[(kc + c) * TW];
            const uint32_t* b1p = &KVs[(kc + c + 4) * TW];
#pragma unroll
            for (int ni = 0; ni < 16; ni++) {
                int n = ni * 8 + r;
                uint32_t bb[2] = { b0p[n], b1p[n] };
                mma_tf32(acc_s[ni], a, bb);
            }
        }

        // Online softmax (rows fully within quad: shuffle over c = xor 1,2)
        float tmax0 = -3.4e38f, tmax1 = -3.4e38f;
#pragma unroll
        for (int ni = 0; ni < 16; ni++) {
#pragma unroll
            for (int q = 0; q < 4; q++) {
                float v = acc_s[ni][q] * scale;
                if (jt == it) {
                    int n = ni * 8 + 2 * c + (q & 1);
                    int m = m0 + 8 * (q >> 1);
                    if (n > m) v = NEG_INF_F;
                }
                acc_s[ni][q] = v;
                if (q < 2) tmax0 = fmaxf(tmax0, v); else tmax1 = fmaxf(tmax1, v);
            }
        }
#pragma unroll
        for (int o = 1; o <= 2; o <<= 1) {
            tmax0 = fmaxf(tmax0, __shfl_xor_sync(0xFFFFFFFFu, tmax0, o));
            tmax1 = fmaxf(tmax1, __shfl_xor_sync(0xFFFFFFFFu, tmax1, o));
        }
        const float mn0 = fmaxf(mprev0, tmax0);
        const float mn1 = fmaxf(mprev1, tmax1);
        const float fc0 = __expf(mprev0 - mn0);
        const float fc1 = __expf(mprev1 - mn1);
        mprev0 = mn0; mprev1 = mn1;

        float s0 = 0.f, s1 = 0.f;
#pragma unroll
        for (int ni = 0; ni < 16; ni++) {
            const int nb = ni * 8 + 2 * c;
            float p0 = __expf(acc_s[ni][0] - mn0);
            float p1 = __expf(acc_s[ni][1] - mn0);
            float p2 = __expf(acc_s[ni][2] - mn1);
            float p3 = __expf(acc_s[ni][3] - mn1);
            s0 += p0 + p1; s1 += p2 + p3;
            Ps[nb * TW + m0]           = f2tf32(p0);
            Ps[(nb + 1) * TW + m0]     = f2tf32(p1);
            Ps[nb * TW + m0 + 8]       = f2tf32(p2);
            Ps[(nb + 1) * TW + m0 + 8] = f2tf32(p3);
        }
#pragma unroll
        for (int o = 1; o <= 2; o <<= 1) {
            s0 += __shfl_xor_sync(0xFFFFFFFFu, s0, o);
            s1 += __shfl_xor_sync(0xFFFFFFFFu, s1, o);
        }
        l0 = l0 * fc0 + s0;
        l1 = l1 * fc1 + s1;
#pragma unroll
        for (int ni = 0; ni < 16; ni++) {
            acc_o[ni][0] *= fc0; acc_o[ni][1] *= fc0;
            acc_o[ni][2] *= fc1; acc_o[ni][3] *= fc1;
        }
        __syncthreads();   // all warps done reading K, P stores visible

        // Load V tile (natural layout): KVs[j][d]
#pragma unroll
        for (int i = 0; i < 16; i++) {
            int f = tid + i * 256;
            int j = f >> 5, d4 = (f & 31) << 2;
            float4 v = *reinterpret_cast<const float4*>(
                VB + (size_t)(jt * 128 + j) * HD + d4);
            *reinterpret_cast<uint4*>(&KVs[j * TW + d4]) =
                make_uint4(f2tf32(v.x), f2tf32(v.y), f2tf32(v.z), f2tf32(v.w));
        }
        __syncthreads();

        // O += P~ V  (k over j=128)
#pragma unroll 2
        for (int kc = 0; kc < 128; kc += 8) {
            uint32_t a[4];
            const uint32_t* p0 = &Ps[(kc + c) * TW];
            const uint32_t* p1 = &Ps[(kc + c + 4) * TW];
            a[0] = p0[m0]; a[1] = p0[m0 + 8]; a[2] = p1[m0]; a[3] = p1[m0 + 8];
            const uint32_t* b0p = &KVs[(kc + c) * TW];
            const uint32_t* b1p = &KVs[(kc + c + 4) * TW];
#pragma unroll
            for (int ni = 0; ni < 16; ni++) {
                int n = ni * 8 + r;
                uint32_t bb[2] = { b0p[n], b1p[n] };
                mma_tf32(acc_o[ni], a, bb);
            }
        }
    }

    // Epilogue: normalize and write O
    const float i0 = 1.f / l0, i1 = 1.f / l1;
    const int srow = it * 128 + m0;
    float* o0 = g_o + ((size_t)b * Sq + srow) * Dq + h * HD;
    float* o1 = g_o + ((size_t)b * Sq + srow + 8) * Dq + h * HD;
#pragma unroll
    for (int ni = 0; ni < 16; ni++) {
        const int d = ni * 8 + 2 * c;
        *reinterpret_cast<float2*>(o0 + d) = make_float2(acc_o[ni][0] * i0, acc_o[ni][1] * i0);
        *reinterpret_cast<float2*>(o1 + d) = make_float2(acc_o[ni][2] * i1, acc_o[ni][3] * i1);
    }
}

// ---------------------------------------------------------------------------
// 4) Output projection
// ---------------------------------------------------------------------------
__global__ void __launch_bounds__(NTHREADS) k_gemm_out(const float* __restrict__ wo,
                                                       float* __restrict__ out)
{
    const int m0 = blockIdx.y * BM, n0 = blockIdx.x * BN;
    float acc[2][8][4] = {};
    mm_tile(g_o + (size_t)m0 * Dq, Dq, wo + (size_t)n0 * Dq, Dq, Dq, acc);

    const int lane = threadIdx.x & 31, wid = threadIdx.x >> 5;
    const int wm = wid >> 1, wn = wid & 1, r = lane >> 2, c = lane & 3;
#pragma unroll
    for (int mi = 0; mi < 2; mi++) {
        const int m = m0 + wm * 32 + mi * 16 + r;
#pragma unroll
        for (int ni = 0; ni < 8; ni++) {
            const int n = n0 + wn * 64 + ni * 8 + 2 * c;
            *reinterpret_cast<float2*>(out + (size_t)m * Dq + n) =
                make_float2(acc[mi][ni][0], acc[mi][ni][1]);
            *reinterpret_cast<float2*>(out + (size_t)(m + 8) * Dq + n) =
                make_float2(acc[mi][ni][2], acc[mi][ni][3]);
        }
    }
}

// ---------------------------------------------------------------------------
// Launch
// ---------------------------------------------------------------------------
extern "C" void kernel_launch(void* const* d_in, const int* in_sizes, int n_in,
                              void* d_out, int out_size)
{
    const float* x     = (const float*)d_in[0];
    const float* w_qkv = (const float*)d_in[1];
    const float* w_o   = (const float*)d_in[2];
    float* out = (float*)d_out;

    cudaFuncSetAttribute(k_flash, cudaFuncAttributeMaxDynamicSharedMemorySize, FLASH_SMEM);

    k_gemm_qkv<<<dim3(QKV_O / BN, MROWS / BM), NTHREADS>>>(x, w_qkv);
    k_rope<<<dim3(Sq, Bq), 256>>>();
    k_flash<<<dim3(16, Bq * NH), NTHREADS, FLASH_SMEM>>>();
    k_gemm_out<<<dim3(Dq / BN, MROWS / BM), NTHREADS>>>(w_o, out);
}

// round 5
// speedup vs baseline: 3.2261x; 1.1773x over previous
#include <cuda_runtime.h>
#include <cuda_bf16.h>
#include <math.h>
#include <cstdint>

// ---------------------------------------------------------------------------
// Problem constants
// ---------------------------------------------------------------------------
#define Bq      2
#define Sq      2048
#define Dq      2048
#define NH      16
#define NKV     4
#define HD      128
#define QKV_O   3072
#define MROWS   (Bq * Sq)
#define NEG_INF_F (-1e9f)

// Projection GEMM tiling (mma.sync m16n8k8 tf32, ldmatrix fragments)
#define BM 128
#define BN 128
#define BK 16
#define NTHREADS 256
#define KST 20                  // smem k-stride (16 + 4 pad) floats

// Flash kernel smem stride: 128 + 4 pad
#define FW 132
#define FLASH_SMEM (3 * 128 * FW * 4)

// ---------------------------------------------------------------------------
// Static scratch
// ---------------------------------------------------------------------------
__device__ float g_qkv[(size_t)MROWS * QKV_O];
__device__ float g_q  [(size_t)Bq * NH  * Sq * HD];   // natural [bh][s][d]
__device__ float g_k  [(size_t)Bq * NKV * Sq * HD];   // natural [bk][s][d]
__device__ float g_v  [(size_t)Bq * NKV * Sq * HD];   // natural [bk][s][d]
__device__ float g_o  [(size_t)MROWS * Dq];           // attn out [b,s,h*hd]

// ---------------------------------------------------------------------------
// Helpers
// ---------------------------------------------------------------------------
__device__ __forceinline__ uint32_t f2tf32(float x) {
    uint32_t r;
    asm("cvt.rna.tf32.f32 %0, %1;" : "=r"(r) : "f"(x));
    return r;
}

__device__ __forceinline__ void mma_tf32(float (&d)[4], const uint32_t (&a)[4],
                                         const uint32_t* b) {
    asm volatile(
        "mma.sync.aligned.m16n8k8.row.col.f32.tf32.tf32.f32 "
        "{%0,%1,%2,%3}, {%4,%5,%6,%7}, {%8,%9}, {%0,%1,%2,%3};"
        : "+f"(d[0]), "+f"(d[1]), "+f"(d[2]), "+f"(d[3])
        : "r"(a[0]), "r"(a[1]), "r"(a[2]), "r"(a[3]), "r"(b[0]), "r"(b[1]));
}

// ldmatrix.x4 on 32-bit data: each 8x8 b16 matrix == one 8x4 tf32 tile,
// distributing element (row l/4, col l%4) to lane l — exactly one mma tf32
// fragment register per matrix.
__device__ __forceinline__ void ldsm_x4(uint32_t* r, uint32_t addr) {
    asm volatile("ldmatrix.sync.aligned.m8n8.x4.shared.b16 {%0,%1,%2,%3}, [%4];"
        : "=r"(r[0]), "=r"(r[1]), "=r"(r[2]), "=r"(r[3]) : "r"(addr));
}

__device__ __forceinline__ uint4 tf32x4(float4 v) {
    return make_uint4(f2tf32(v.x), f2tf32(v.y), f2tf32(v.z), f2tf32(v.w));
}

// ---------------------------------------------------------------------------
// Projection NT GEMM tile:  C(128x128) += A[128,K](K-major) * B[128,K]^T
// smem layout [row][k] stride KST=20; fragments via ldmatrix.x4.
// 8 warps 4(M)x2(N); warp tile 32x64. Reg-prefetch double buffered.
// ---------------------------------------------------------------------------
__device__ __forceinline__ void mm_tile(const float* __restrict__ A, int lda,
                                        const float* __restrict__ B, int ldb,
                                        int kCount, float (&acc)[2][8][4])
{
    __shared__ uint32_t As[128 * KST];
    __shared__ uint32_t Bs[128 * KST];

    const int tid  = threadIdx.x;
    const int lane = tid & 31;
    const int wid  = tid >> 5;
    const int wm   = wid >> 1;
    const int wn   = wid & 1;
    const int lr   = lane & 7;
    const int sub  = lane >> 3;

    // STS mapping: thread covers rows row0 and row0+64, 4 consecutive k.
    const int row0 = tid >> 2, c4 = (tid & 3) << 2;
    const int row1 = row0 + 64;

    // ldmatrix per-lane source addresses (bytes); += ks*4 per k-step.
    const uint32_t asb = (uint32_t)__cvta_generic_to_shared(As);
    const uint32_t bsb = (uint32_t)__cvta_generic_to_shared(Bs);
    const uint32_t aA0 = asb + (((wm * 32 + lr + (sub & 1) * 8) * KST + (sub >> 1) * 4) << 2);
    const uint32_t aA1 = aA0 + 16 * KST * 4;
    uint32_t bA[4];
#pragma unroll
    for (int pi = 0; pi < 4; pi++)
        bA[pi] = bsb + (((wn * 64 + pi * 16 + lr + (sub >> 1) * 8) * KST + (sub & 1) * 4) << 2);

    float4 pa0 = *reinterpret_cast<const float4*>(A + (size_t)row0 * lda + c4);
    float4 pa1 = *reinterpret_cast<const float4*>(A + (size_t)row1 * lda + c4);
    float4 pb0 = *reinterpret_cast<const float4*>(B + (size_t)row0 * ldb + c4);
    float4 pb1 = *reinterpret_cast<const float4*>(B + (size_t)row1 * ldb + c4);

    for (int k0 = 0; k0 < kCount; k0 += BK) {
        *reinterpret_cast<uint4*>(&As[row0 * KST + c4]) = tf32x4(pa0);
        *reinterpret_cast<uint4*>(&As[row1 * KST + c4]) = tf32x4(pa1);
        *reinterpret_cast<uint4*>(&Bs[row0 * KST + c4]) = tf32x4(pb0);
        *reinterpret_cast<uint4*>(&Bs[row1 * KST + c4]) = tf32x4(pb1);
        __syncthreads();

        const int kn = k0 + BK;
        if (kn < kCount) {
            pa0 = *reinterpret_cast<const float4*>(A + (size_t)row0 * lda + kn + c4);
            pa1 = *reinterpret_cast<const float4*>(A + (size_t)row1 * lda + kn + c4);
            pb0 = *reinterpret_cast<const float4*>(B + (size_t)row0 * ldb + kn + c4);
            pb1 = *reinterpret_cast<const float4*>(B + (size_t)row1 * ldb + kn + c4);
        }

#pragma unroll
        for (int ks = 0; ks < BK; ks += 8) {
            uint32_t a0[4], a1[4];
            ldsm_x4(a0, aA0 + ks * 4);
            ldsm_x4(a1, aA1 + ks * 4);
#pragma unroll
            for (int pi = 0; pi < 4; pi++) {
                uint32_t bq[4];
                ldsm_x4(bq, bA[pi] + ks * 4);
                mma_tf32(acc[0][2 * pi],     a0, bq);
                mma_tf32(acc[0][2 * pi + 1], a0, bq + 2);
                mma_tf32(acc[1][2 * pi],     a1, bq);
                mma_tf32(acc[1][2 * pi + 1], a1, bq + 2);
            }
        }
        __syncthreads();
    }
}

// ---------------------------------------------------------------------------
// 1) QKV projection
// ---------------------------------------------------------------------------
__global__ void __launch_bounds__(NTHREADS) k_gemm_qkv(const float* __restrict__ x,
                                                       const float* __restrict__ w)
{
    const int m0 = blockIdx.y * BM, n0 = blockIdx.x * BN;
    float acc[2][8][4] = {};
    mm_tile(x + (size_t)m0 * Dq, Dq, w + (size_t)n0 * Dq, Dq, Dq, acc);

    const int lane = threadIdx.x & 31, wid = threadIdx.x >> 5;
    const int wm = wid >> 1, wn = wid & 1, r = lane >> 2, c = lane & 3;
#pragma unroll
    for (int mi = 0; mi < 2; mi++) {
        const int m = m0 + wm * 32 + mi * 16 + r;
#pragma unroll
        for (int ni = 0; ni < 8; ni++) {
            const int n = n0 + wn * 64 + ni * 8 + 2 * c;
            *reinterpret_cast<float2*>(g_qkv + (size_t)m * QKV_O + n) =
                make_float2(acc[mi][ni][0], acc[mi][ni][1]);
            *reinterpret_cast<float2*>(g_qkv + (size_t)(m + 8) * QKV_O + n) =
                make_float2(acc[mi][ni][2], acc[mi][ni][3]);
        }
    }
}

// ---------------------------------------------------------------------------
// 2) RoPE + scatter (all natural [.][s][d] layouts)
// ---------------------------------------------------------------------------
__global__ void k_rope()
{
    const int s = blockIdx.x, b = blockIdx.y;
    const float* row = g_qkv + ((size_t)b * Sq + s) * QKV_O;
    __shared__ float cs[HD / 2], sn[HD / 2];
    const int tid = threadIdx.x;
    if (tid < HD / 2) {
        double invf = pow(10000.0, -((double)(2 * tid) / (double)HD));
        double ang  = (double)s * invf;
        cs[tid] = (float)cos(ang);
        sn[tid] = (float)sin(ang);
    }
    __syncthreads();
    for (int p = tid; p < NH * (HD / 2); p += 256) {
        int h = p >> 6, i = p & 63;
        float v0 = row[h * HD + 2 * i], v1 = row[h * HD + 2 * i + 1];
        float* qd = g_q + ((size_t)(b * NH + h) * Sq + s) * HD;
        qd[2 * i]     = v0 * cs[i] - v1 * sn[i];
        qd[2 * i + 1] = v0 * sn[i] + v1 * cs[i];
    }
    for (int p = tid; p < NKV * (HD / 2); p += 256) {
        int h = p >> 6, i = p & 63;
        float v0 = row[NH * HD + h * HD + 2 * i], v1 = row[NH * HD + h * HD + 2 * i + 1];
        float* kd = g_k + ((size_t)(b * NKV + h) * Sq + s) * HD;
        kd[2 * i]     = v0 * cs[i] - v1 * sn[i];
        kd[2 * i + 1] = v0 * sn[i] + v1 * cs[i];
    }
    for (int p = tid; p < NKV * HD; p += 256) {
        int h = p >> 7, d = p & 127;
        g_v[((size_t)(b * NKV + h) * Sq + s) * HD + d] = row[(NH + NKV) * HD + p];
    }
}

// ---------------------------------------------------------------------------
// 3) Fused flash attention. 8 warps, warp tile 16(M) x 128(N).
//    Qs[m][d], Ps[m][j], KVs: K as [n][d], V as [j][d]; stride FW=132.
// ---------------------------------------------------------------------------
__global__ void __launch_bounds__(NTHREADS, 1) k_flash()
{
    extern __shared__ uint32_t sm[];
    uint32_t* Qs  = sm;
    uint32_t* Ps  = sm + 128 * FW;
    uint32_t* KVs = sm + 2 * 128 * FW;

    const int it = 15 - blockIdx.x;           // heavy tiles first
    const int bh = blockIdx.y;
    const int b = bh >> 4, h = bh & 15, hk = h >> 2;
    const int tid = threadIdx.x, lane = tid & 31, w = tid >> 5;
    const int r = lane >> 2, c = lane & 3;
    const int lr = lane & 7, sub = lane >> 3;
    const int m0 = w * 16 + r;

    // ldmatrix source addresses
    const uint32_t qsb = (uint32_t)__cvta_generic_to_shared(Qs);
    const uint32_t psb = (uint32_t)__cvta_generic_to_shared(Ps);
    const uint32_t ksb = (uint32_t)__cvta_generic_to_shared(KVs);
    const uint32_t aQ = qsb + (((w * 16 + lr + (sub & 1) * 8) * FW + (sub >> 1) * 4) << 2);
    const uint32_t aP = psb + (((w * 16 + lr + (sub & 1) * 8) * FW + (sub >> 1) * 4) << 2);
    uint32_t bK[8];
#pragma unroll
    for (int pi = 0; pi < 8; pi++)
        bK[pi] = ksb + (((pi * 16 + lr + (sub >> 1) * 8) * FW + (sub & 1) * 4) << 2);

    // Load Q tile (natural layout): Qs[m][d]
    const float* Qp = g_q + ((size_t)bh * Sq + (size_t)it * 128) * HD;
#pragma unroll
    for (int i = 0; i < 16; i++) {
        int f = tid + i * 256;
        int m = f >> 5, d4 = (f & 31) << 2;
        float4 v = *reinterpret_cast<const float4*>(Qp + (size_t)m * HD + d4);
        *reinterpret_cast<uint4*>(&Qs[m * FW + d4]) = tf32x4(v);
    }

    float acc_o[16][4] = {};
    float mprev0 = -1e30f, mprev1 = -1e30f;
    float l0 = 0.f, l1 = 0.f;
    const float scale = 0.08838834764831845f;

    const float* KB = g_k + (size_t)(b * NKV + hk) * Sq * HD;
    const float* VB = g_v + (size_t)(b * NKV + hk) * Sq * HD;

    for (int jt = 0; jt <= it; jt++) {
        __syncthreads();   // prev AV done with KVs/Ps (and Q stores on iter 0)

        // Load K tile: KVs[n][d]
#pragma unroll
        for (int i = 0; i < 16; i++) {
            int f = tid + i * 256;
            int n = f >> 5, d4 = (f & 31) << 2;
            float4 v = *reinterpret_cast<const float4*>(
                KB + (size_t)(jt * 128 + n) * HD + d4);
            *reinterpret_cast<uint4*>(&KVs[n * FW + d4]) = tf32x4(v);
        }
        __syncthreads();

        // S = Q K^T (k over d=128)
        float acc_s[16][4] = {};
#pragma unroll 4
        for (int kc = 0; kc < 128; kc += 8) {
            uint32_t a[4];
            ldsm_x4(a, aQ + kc * 4);
#pragma unroll
            for (int pi = 0; pi < 8; pi++) {
                uint32_t bq[4];
                ldsm_x4(bq, bK[pi] + kc * 4);
                mma_tf32(acc_s[2 * pi],     a, bq);
                mma_tf32(acc_s[2 * pi + 1], a, bq + 2);
            }
        }

        // Online softmax (row reductions within quad: xor 1,2)
        float tmax0 = -3.4e38f, tmax1 = -3.4e38f;
#pragma unroll
        for (int ni = 0; ni < 16; ni++) {
#pragma unroll
            for (int q = 0; q < 4; q++) {
                float v = acc_s[ni][q] * scale;
                if (jt == it) {
                    int n = ni * 8 + 2 * c + (q & 1);
                    int m = m0 + 8 * (q >> 1);
                    if (n > m) v = NEG_INF_F;
                }
                acc_s[ni][q] = v;
                if (q < 2) tmax0 = fmaxf(tmax0, v); else tmax1 = fmaxf(tmax1, v);
            }
        }
#pragma unroll
        for (int o = 1; o <= 2; o <<= 1) {
            tmax0 = fmaxf(tmax0, __shfl_xor_sync(0xFFFFFFFFu, tmax0, o));
            tmax1 = fmaxf(tmax1, __shfl_xor_sync(0xFFFFFFFFu, tmax1, o));
        }
        const float mn0 = fmaxf(mprev0, tmax0);
        const float mn1 = fmaxf(mprev1, tmax1);
        const float fc0 = __expf(mprev0 - mn0);
        const float fc1 = __expf(mprev1 - mn1);
        mprev0 = mn0; mprev1 = mn1;

        float s0 = 0.f, s1 = 0.f;
#pragma unroll
        for (int ni = 0; ni < 16; ni++) {
            const int nb = ni * 8 + 2 * c;
            float p0 = __expf(acc_s[ni][0] - mn0);
            float p1 = __expf(acc_s[ni][1] - mn0);
            float p2 = __expf(acc_s[ni][2] - mn1);
            float p3 = __expf(acc_s[ni][3] - mn1);
            s0 += p0 + p1; s1 += p2 + p3;
            *reinterpret_cast<uint2*>(&Ps[m0 * FW + nb]) =
                make_uint2(f2tf32(p0), f2tf32(p1));
            *reinterpret_cast<uint2*>(&Ps[(m0 + 8) * FW + nb]) =
                make_uint2(f2tf32(p2), f2tf32(p3));
        }
#pragma unroll
        for (int o = 1; o <= 2; o <<= 1) {
            s0 += __shfl_xor_sync(0xFFFFFFFFu, s0, o);
            s1 += __shfl_xor_sync(0xFFFFFFFFu, s1, o);
        }
        l0 = l0 * fc0 + s0;
        l1 = l1 * fc1 + s1;
#pragma unroll
        for (int ni = 0; ni < 16; ni++) {
            acc_o[ni][0] *= fc0; acc_o[ni][1] *= fc0;
            acc_o[ni][2] *= fc1; acc_o[ni][3] *= fc1;
        }
        __syncthreads();   // K reads done, P stores visible

        // Load V tile: KVs[j][d]
#pragma unroll
        for (int i = 0; i < 16; i++) {
            int f = tid + i * 256;
            int j = f >> 5, d4 = (f & 31) << 2;
            float4 v = *reinterpret_cast<const float4*>(
                VB + (size_t)(jt * 128 + j) * HD + d4);
            *reinterpret_cast<uint4*>(&KVs[j * FW + d4]) = tf32x4(v);
        }
        __syncthreads();

        // O += P~ V (k over j=128); A via ldmatrix, B scalar from [j][d]
#pragma unroll 2
        for (int kc = 0; kc < 128; kc += 8) {
            uint32_t a[4];
            ldsm_x4(a, aP + kc * 4);
            const uint32_t* b0p = &KVs[(kc + c) * FW];
            const uint32_t* b1p = &KVs[(kc + c + 4) * FW];
#pragma unroll
            for (int ni = 0; ni < 16; ni++) {
                int n = ni * 8 + r;
                uint32_t bb[2] = { b0p[n], b1p[n] };
                mma_tf32(acc_o[ni], a, bb);
            }
        }
    }

    // Epilogue: normalize and write O
    const float i0 = 1.f / l0, i1 = 1.f / l1;
    const int srow = it * 128 + m0;
    float* o0 = g_o + ((size_t)b * Sq + srow) * Dq + h * HD;
    float* o1 = g_o + ((size_t)b * Sq + srow + 8) * Dq + h * HD;
#pragma unroll
    for (int ni = 0; ni < 16; ni++) {
        const int d = ni * 8 + 2 * c;
        *reinterpret_cast<float2*>(o0 + d) = make_float2(acc_o[ni][0] * i0, acc_o[ni][1] * i0);
        *reinterpret_cast<float2*>(o1 + d) = make_float2(acc_o[ni][2] * i1, acc_o[ni][3] * i1);
    }
}

// ---------------------------------------------------------------------------
// 4) Output projection
// ---------------------------------------------------------------------------
__global__ void __launch_bounds__(NTHREADS) k_gemm_out(const float* __restrict__ wo,
                                                       float* __restrict__ out)
{
    const int m0 = blockIdx.y * BM, n0 = blockIdx.x * BN;
    float acc[2][8][4] = {};
    mm_tile(g_o + (size_t)m0 * Dq, Dq, wo + (size_t)n0 * Dq, Dq, Dq, acc);

    const int lane = threadIdx.x & 31, wid = threadIdx.x >> 5;
    const int wm = wid >> 1, wn = wid & 1, r = lane >> 2, c = lane & 3;
#pragma unroll
    for (int mi = 0; mi < 2; mi++) {
        const int m = m0 + wm * 32 + mi * 16 + r;
#pragma unroll
        for (int ni = 0; ni < 8; ni++) {
            const int n = n0 + wn * 64 + ni * 8 + 2 * c;
            *reinterpret_cast<float2*>(out + (size_t)m * Dq + n) =
                make_float2(acc[mi][ni][0], acc[mi][ni][1]);
            *reinterpret_cast<float2*>(out + (size_t)(m + 8) * Dq + n) =
                make_float2(acc[mi][ni][2], acc[mi][ni][3]);
        }
    }
}

// ---------------------------------------------------------------------------
// Launch
// ---------------------------------------------------------------------------
extern "C" void kernel_launch(void* const* d_in, const int* in_sizes, int n_in,
                              void* d_out, int out_size)
{
    const float* x     = (const float*)d_in[0];
    const float* w_qkv = (const float*)d_in[1];
    const float* w_o   = (const float*)d_in[2];
    float* out = (float*)d_out;

    cudaFuncSetAttribute(k_flash, cudaFuncAttributeMaxDynamicSharedMemorySize, FLASH_SMEM);

    k_gemm_qkv<<<dim3(QKV_O / BN, MROWS / BM), NTHREADS>>>(x, w_qkv);
    k_rope<<<dim3(Sq, Bq), 256>>>();
    k_flash<<<dim3(16, Bq * NH), NTHREADS, FLASH_SMEM>>>();
    k_gemm_out<<<dim3(Dq / BN, MROWS / BM), NTHREADS>>>(w_o, out);
}

// round 6
// speedup vs baseline: 3.5344x; 1.0956x over previous
#include <cuda_runtime.h>
#include <cuda_bf16.h>
#include <math.h>
#include <cstdint>

// ---------------------------------------------------------------------------
// Problem constants
// ---------------------------------------------------------------------------
#define Bq      2
#define Sq      2048
#define Dq      2048
#define NH      16
#define NKV     4
#define HD      128
#define QKV_O   3072
#define MROWS   (Bq * Sq)
#define NEG_INF_F (-1e9f)

// Projection GEMM tiling (mma.sync m16n8k8 tf32, ldmatrix fragments)
#define BM 128
#define BN 128
#define BK 16
#define NTHREADS 256
#define KST 20                  // smem k-stride (16 + 4 pad) floats
#define KSTAGE (128 * KST)      // u32 elements per stage

// Flash kernel smem stride: 128 + 4 pad
#define FW 132
#define FLASH_SMEM (3 * 128 * FW * 4)

// ---------------------------------------------------------------------------
// Static scratch
// ---------------------------------------------------------------------------
__device__ float g_qkv[(size_t)MROWS * QKV_O];
__device__ float g_q  [(size_t)Bq * NH  * Sq * HD];   // natural [bh][s][d]
__device__ float g_k  [(size_t)Bq * NKV * Sq * HD];   // natural [bk][s][d]
__device__ float g_v  [(size_t)Bq * NKV * Sq * HD];   // natural [bk][s][d]
__device__ float g_o  [(size_t)MROWS * Dq];           // attn out [b,s,h*hd]

// ---------------------------------------------------------------------------
// Helpers
// ---------------------------------------------------------------------------
__device__ __forceinline__ uint32_t f2tf32(float x) {
    uint32_t r;
    asm("cvt.rna.tf32.f32 %0, %1;" : "=r"(r) : "f"(x));
    return r;
}

__device__ __forceinline__ void mma_tf32(float (&d)[4], const uint32_t (&a)[4],
                                         const uint32_t* b) {
    asm volatile(
        "mma.sync.aligned.m16n8k8.row.col.f32.tf32.tf32.f32 "
        "{%0,%1,%2,%3}, {%4,%5,%6,%7}, {%8,%9}, {%0,%1,%2,%3};"
        : "+f"(d[0]), "+f"(d[1]), "+f"(d[2]), "+f"(d[3])
        : "r"(a[0]), "r"(a[1]), "r"(a[2]), "r"(a[3]), "r"(b[0]), "r"(b[1]));
}

// ldmatrix.x4 on 32-bit data: each 8x8 b16 matrix == one 8x4 tf32 tile.
__device__ __forceinline__ void ldsm_x4(uint32_t* r, uint32_t addr) {
    asm volatile("ldmatrix.sync.aligned.m8n8.x4.shared.b16 {%0,%1,%2,%3}, [%4];"
        : "=r"(r[0]), "=r"(r[1]), "=r"(r[2]), "=r"(r[3]) : "r"(addr));
}

__device__ __forceinline__ uint4 tf32x4(float4 v) {
    return make_uint4(f2tf32(v.x), f2tf32(v.y), f2tf32(v.z), f2tf32(v.w));
}

// ---------------------------------------------------------------------------
// Projection NT GEMM tile:  C(128x128) += A[128,K](K-major) * B[128,K]^T
// 2-stage smem double buffer, one barrier per K-chunk; ldmatrix fragments.
// 8 warps 4(M)x2(N); warp tile 32x64.
// ---------------------------------------------------------------------------
__device__ __forceinline__ void mm_tile(const float* __restrict__ A, int lda,
                                        const float* __restrict__ B, int ldb,
                                        int kCount, float (&acc)[2][8][4])
{
    __shared__ uint32_t As[2 * KSTAGE];
    __shared__ uint32_t Bs[2 * KSTAGE];

    const int tid  = threadIdx.x;
    const int lane = tid & 31;
    const int wid  = tid >> 5;
    const int wm   = wid >> 1;
    const int wn   = wid & 1;
    const int lr   = lane & 7;
    const int sub  = lane >> 3;

    // STS mapping: thread covers rows row0 and row0+64, 4 consecutive k.
    const int row0 = tid >> 2, c4 = (tid & 3) << 2;
    const int row1 = row0 + 64;

    // ldmatrix per-lane source addresses (stage 0, bytes)
    const uint32_t asb = (uint32_t)__cvta_generic_to_shared(As);
    const uint32_t bsb = (uint32_t)__cvta_generic_to_shared(Bs);
    const uint32_t aA0 = asb + (((wm * 32 + lr + (sub & 1) * 8) * KST + (sub >> 1) * 4) << 2);
    const uint32_t aA1 = aA0 + 16 * KST * 4;
    uint32_t bA[4];
#pragma unroll
    for (int pi = 0; pi < 4; pi++)
        bA[pi] = bsb + (((wn * 64 + pi * 16 + lr + (sub >> 1) * 8) * KST + (sub & 1) * 4) << 2);

    // Prologue: load chunk 0 and stage it into buffer 0
    float4 pa0 = *reinterpret_cast<const float4*>(A + (size_t)row0 * lda + c4);
    float4 pa1 = *reinterpret_cast<const float4*>(A + (size_t)row1 * lda + c4);
    float4 pb0 = *reinterpret_cast<const float4*>(B + (size_t)row0 * ldb + c4);
    float4 pb1 = *reinterpret_cast<const float4*>(B + (size_t)row1 * ldb + c4);
    *reinterpret_cast<uint4*>(&As[row0 * KST + c4]) = tf32x4(pa0);
    *reinterpret_cast<uint4*>(&As[row1 * KST + c4]) = tf32x4(pa1);
    *reinterpret_cast<uint4*>(&Bs[row0 * KST + c4]) = tf32x4(pb0);
    *reinterpret_cast<uint4*>(&Bs[row1 * KST + c4]) = tf32x4(pb1);

    int st = 0;
    for (int k0 = 0; k0 < kCount; k0 += BK) {
        __syncthreads();                     // stage st ready for all
        const int kn = k0 + BK;
        if (kn < kCount) {                   // issue next chunk's LDGs now
            pa0 = *reinterpret_cast<const float4*>(A + (size_t)row0 * lda + kn + c4);
            pa1 = *reinterpret_cast<const float4*>(A + (size_t)row1 * lda + kn + c4);
            pb0 = *reinterpret_cast<const float4*>(B + (size_t)row0 * ldb + kn + c4);
            pb1 = *reinterpret_cast<const float4*>(B + (size_t)row1 * ldb + kn + c4);
        }

        const uint32_t so = (uint32_t)st * (KSTAGE * 4);   // stage byte offset
#pragma unroll
        for (int ks = 0; ks < BK; ks += 8) {
            uint32_t a0[4], a1[4];
            ldsm_x4(a0, aA0 + so + ks * 4);
            ldsm_x4(a1, aA1 + so + ks * 4);
#pragma unroll
            for (int pi = 0; pi < 4; pi++) {
                uint32_t bq[4];
                ldsm_x4(bq, bA[pi] + so + ks * 4);
                mma_tf32(acc[0][2 * pi],     a0, bq);
                mma_tf32(acc[0][2 * pi + 1], a0, bq + 2);
                mma_tf32(acc[1][2 * pi],     a1, bq);
                mma_tf32(acc[1][2 * pi + 1], a1, bq + 2);
            }
        }

        if (kn < kCount) {                   // stage next chunk into st^1
            uint32_t* Ad = &As[(st ^ 1) * KSTAGE];
            uint32_t* Bd = &Bs[(st ^ 1) * KSTAGE];
            *reinterpret_cast<uint4*>(&Ad[row0 * KST + c4]) = tf32x4(pa0);
            *reinterpret_cast<uint4*>(&Ad[row1 * KST + c4]) = tf32x4(pa1);
            *reinterpret_cast<uint4*>(&Bd[row0 * KST + c4]) = tf32x4(pb0);
            *reinterpret_cast<uint4*>(&Bd[row1 * KST + c4]) = tf32x4(pb1);
        }
        st ^= 1;
    }
}

// ---------------------------------------------------------------------------
// 1) QKV projection
// ---------------------------------------------------------------------------
__global__ void __launch_bounds__(NTHREADS, 2) k_gemm_qkv(const float* __restrict__ x,
                                                          const float* __restrict__ w)
{
    const int m0 = blockIdx.y * BM, n0 = blockIdx.x * BN;
    float acc[2][8][4] = {};
    mm_tile(x + (size_t)m0 * Dq, Dq, w + (size_t)n0 * Dq, Dq, Dq, acc);

    const int lane = threadIdx.x & 31, wid = threadIdx.x >> 5;
    const int wm = wid >> 1, wn = wid & 1, r = lane >> 2, c = lane & 3;
#pragma unroll
    for (int mi = 0; mi < 2; mi++) {
        const int m = m0 + wm * 32 + mi * 16 + r;
#pragma unroll
        for (int ni = 0; ni < 8; ni++) {
            const int n = n0 + wn * 64 + ni * 8 + 2 * c;
            *reinterpret_cast<float2*>(g_qkv + (size_t)m * QKV_O + n) =
                make_float2(acc[mi][ni][0], acc[mi][ni][1]);
            *reinterpret_cast<float2*>(g_qkv + (size_t)(m + 8) * QKV_O + n) =
                make_float2(acc[mi][ni][2], acc[mi][ni][3]);
        }
    }
}

// ---------------------------------------------------------------------------
// 2) RoPE + scatter (all natural [.][s][d] layouts)
// ---------------------------------------------------------------------------
__global__ void k_rope()
{
    const int s = blockIdx.x, b = blockIdx.y;
    const float* row = g_qkv + ((size_t)b * Sq + s) * QKV_O;
    __shared__ float cs[HD / 2], sn[HD / 2];
    const int tid = threadIdx.x;
    if (tid < HD / 2) {
        double invf = pow(10000.0, -((double)(2 * tid) / (double)HD));
        double ang  = (double)s * invf;
        cs[tid] = (float)cos(ang);
        sn[tid] = (float)sin(ang);
    }
    __syncthreads();
    for (int p = tid; p < NH * (HD / 2); p += 256) {
        int h = p >> 6, i = p & 63;
        float v0 = row[h * HD + 2 * i], v1 = row[h * HD + 2 * i + 1];
        float* qd = g_q + ((size_t)(b * NH + h) * Sq + s) * HD;
        qd[2 * i]     = v0 * cs[i] - v1 * sn[i];
        qd[2 * i + 1] = v0 * sn[i] + v1 * cs[i];
    }
    for (int p = tid; p < NKV * (HD / 2); p += 256) {
        int h = p >> 6, i = p & 63;
        float v0 = row[NH * HD + h * HD + 2 * i], v1 = row[NH * HD + h * HD + 2 * i + 1];
        float* kd = g_k + ((size_t)(b * NKV + h) * Sq + s) * HD;
        kd[2 * i]     = v0 * cs[i] - v1 * sn[i];
        kd[2 * i + 1] = v0 * sn[i] + v1 * cs[i];
    }
    for (int p = tid; p < NKV * HD; p += 256) {
        int h = p >> 7, d = p & 127;
        g_v[((size_t)(b * NKV + h) * Sq + s) * HD + d] = row[(NH + NKV) * HD + p];
    }
}

// ---------------------------------------------------------------------------
// 3) Fused flash attention. 8 warps, warp tile 16(M) x 128(N).
//    Qs[m][d], Ps[m][j], KVs: K as [n][d], V as [j][d]; stride FW=132.
// ---------------------------------------------------------------------------
__global__ void __launch_bounds__(NTHREADS, 1) k_flash()
{
    extern __shared__ uint32_t sm[];
    uint32_t* Qs  = sm;
    uint32_t* Ps  = sm + 128 * FW;
    uint32_t* KVs = sm + 2 * 128 * FW;

    const int it = 15 - blockIdx.x;           // heavy tiles first
    const int bh = blockIdx.y;
    const int b = bh >> 4, h = bh & 15, hk = h >> 2;
    const int tid = threadIdx.x, lane = tid & 31, w = tid >> 5;
    const int r = lane >> 2, c = lane & 3;
    const int lr = lane & 7, sub = lane >> 3;
    const int m0 = w * 16 + r;

    // ldmatrix source addresses
    const uint32_t qsb = (uint32_t)__cvta_generic_to_shared(Qs);
    const uint32_t psb = (uint32_t)__cvta_generic_to_shared(Ps);
    const uint32_t ksb = (uint32_t)__cvta_generic_to_shared(KVs);
    const uint32_t aQ = qsb + (((w * 16 + lr + (sub & 1) * 8) * FW + (sub >> 1) * 4) << 2);
    const uint32_t aP = psb + (((w * 16 + lr + (sub & 1) * 8) * FW + (sub >> 1) * 4) << 2);
    uint32_t bK[8];
#pragma unroll
    for (int pi = 0; pi < 8; pi++)
        bK[pi] = ksb + (((pi * 16 + lr + (sub >> 1) * 8) * FW + (sub & 1) * 4) << 2);

    // Load Q tile (natural layout): Qs[m][d]
    const float* Qp = g_q + ((size_t)bh * Sq + (size_t)it * 128) * HD;
#pragma unroll
    for (int i = 0; i < 16; i++) {
        int f = tid + i * 256;
        int m = f >> 5, d4 = (f & 31) << 2;
        float4 v = *reinterpret_cast<const float4*>(Qp + (size_t)m * HD + d4);
        *reinterpret_cast<uint4*>(&Qs[m * FW + d4]) = tf32x4(v);
    }

    float acc_o[16][4] = {};
    float mprev0 = -1e30f, mprev1 = -1e30f;
    float l0 = 0.f, l1 = 0.f;
    const float scale = 0.08838834764831845f;

    const float* KB = g_k + (size_t)(b * NKV + hk) * Sq * HD;
    const float* VB = g_v + (size_t)(b * NKV + hk) * Sq * HD;

    for (int jt = 0; jt <= it; jt++) {
        __syncthreads();   // prev AV done with KVs/Ps (and Q stores on iter 0)

        // Load K tile: KVs[n][d]
#pragma unroll
        for (int i = 0; i < 16; i++) {
            int f = tid + i * 256;
            int n = f >> 5, d4 = (f & 31) << 2;
            float4 v = *reinterpret_cast<const float4*>(
                KB + (size_t)(jt * 128 + n) * HD + d4);
            *reinterpret_cast<uint4*>(&KVs[n * FW + d4]) = tf32x4(v);
        }
        __syncthreads();

        // S = Q K^T (k over d=128)
        float acc_s[16][4] = {};
#pragma unroll 4
        for (int kc = 0; kc < 128; kc += 8) {
            uint32_t a[4];
            ldsm_x4(a, aQ + kc * 4);
#pragma unroll
            for (int pi = 0; pi < 8; pi++) {
                uint32_t bq[4];
                ldsm_x4(bq, bK[pi] + kc * 4);
                mma_tf32(acc_s[2 * pi],     a, bq);
                mma_tf32(acc_s[2 * pi + 1], a, bq + 2);
            }
        }

        // Online softmax (row reductions within quad: xor 1,2)
        float tmax0 = -3.4e38f, tmax1 = -3.4e38f;
#pragma unroll
        for (int ni = 0; ni < 16; ni++) {
#pragma unroll
            for (int q = 0; q < 4; q++) {
                float v = acc_s[ni][q] * scale;
                if (jt == it) {
                    int n = ni * 8 + 2 * c + (q & 1);
                    int m = m0 + 8 * (q >> 1);
                    if (n > m) v = NEG_INF_F;
                }
                acc_s[ni][q] = v;
                if (q < 2) tmax0 = fmaxf(tmax0, v); else tmax1 = fmaxf(tmax1, v);
            }
        }
#pragma unroll
        for (int o = 1; o <= 2; o <<= 1) {
            tmax0 = fmaxf(tmax0, __shfl_xor_sync(0xFFFFFFFFu, tmax0, o));
            tmax1 = fmaxf(tmax1, __shfl_xor_sync(0xFFFFFFFFu, tmax1, o));
        }
        const float mn0 = fmaxf(mprev0, tmax0);
        const float mn1 = fmaxf(mprev1, tmax1);
        const float fc0 = __expf(mprev0 - mn0);
        const float fc1 = __expf(mprev1 - mn1);
        mprev0 = mn0; mprev1 = mn1;

        float s0 = 0.f, s1 = 0.f;
#pragma unroll
        for (int ni = 0; ni < 16; ni++) {
            const int nb = ni * 8 + 2 * c;
            float p0 = __expf(acc_s[ni][0] - mn0);
            float p1 = __expf(acc_s[ni][1] - mn0);
            float p2 = __expf(acc_s[ni][2] - mn1);
            float p3 = __expf(acc_s[ni][3] - mn1);
            s0 += p0 + p1; s1 += p2 + p3;
            *reinterpret_cast<uint2*>(&Ps[m0 * FW + nb]) =
                make_uint2(f2tf32(p0), f2tf32(p1));
            *reinterpret_cast<uint2*>(&Ps[(m0 + 8) * FW + nb]) =
                make_uint2(f2tf32(p2), f2tf32(p3));
        }
#pragma unroll
        for (int o = 1; o <= 2; o <<= 1) {
            s0 += __shfl_xor_sync(0xFFFFFFFFu, s0, o);
            s1 += __shfl_xor_sync(0xFFFFFFFFu, s1, o);
        }
        l0 = l0 * fc0 + s0;
        l1 = l1 * fc1 + s1;
#pragma unroll
        for (int ni = 0; ni < 16; ni++) {
            acc_o[ni][0] *= fc0; acc_o[ni][1] *= fc0;
            acc_o[ni][2] *= fc1; acc_o[ni][3] *= fc1;
        }
        __syncthreads();   // K reads done, P stores visible

        // Load V tile: KVs[j][d]
#pragma unroll
        for (int i = 0; i < 16; i++) {
            int f = tid + i * 256;
            int j = f >> 5, d4 = (f & 31) << 2;
            float4 v = *reinterpret_cast<const float4*>(
                VB + (size_t)(jt * 128 + j) * HD + d4);
            *reinterpret_cast<uint4*>(&KVs[j * FW + d4]) = tf32x4(v);
        }
        __syncthreads();

        // O += P~ V (k over j=128); A via ldmatrix, B scalar from [j][d]
#pragma unroll 2
        for (int kc = 0; kc < 128; kc += 8) {
            uint32_t a[4];
            ldsm_x4(a, aP + kc * 4);
            const uint32_t* b0p = &KVs[(kc + c) * FW];
            const uint32_t* b1p = &KVs[(kc + c + 4) * FW];
#pragma unroll
            for (int ni = 0; ni < 16; ni++) {
                int n = ni * 8 + r;
                uint32_t bb[2] = { b0p[n], b1p[n] };
                mma_tf32(acc_o[ni], a, bb);
            }
        }
    }

    // Epilogue: normalize and write O
    const float i0 = 1.f / l0, i1 = 1.f / l1;
    const int srow = it * 128 + m0;
    float* o0 = g_o + ((size_t)b * Sq + srow) * Dq + h * HD;
    float* o1 = g_o + ((size_t)b * Sq + srow + 8) * Dq + h * HD;
#pragma unroll
    for (int ni = 0; ni < 16; ni++) {
        const int d = ni * 8 + 2 * c;
        *reinterpret_cast<float2*>(o0 + d) = make_float2(acc_o[ni][0] * i0, acc_o[ni][1] * i0);
        *reinterpret_cast<float2*>(o1 + d) = make_float2(acc_o[ni][2] * i1, acc_o[ni][3] * i1);
    }
}

// ---------------------------------------------------------------------------
// 4) Output projection
// ---------------------------------------------------------------------------
__global__ void __launch_bounds__(NTHREADS, 2) k_gemm_out(const float* __restrict__ wo,
                                                          float* __restrict__ out)
{
    const int m0 = blockIdx.y * BM, n0 = blockIdx.x * BN;
    float acc[2][8][4] = {};
    mm_tile(g_o + (size_t)m0 * Dq, Dq, wo + (size_t)n0 * Dq, Dq, Dq, acc);

    const int lane = threadIdx.x & 31, wid = threadIdx.x >> 5;
    const int wm = wid >> 1, wn = wid & 1, r = lane >> 2, c = lane & 3;
#pragma unroll
    for (int mi = 0; mi < 2; mi++) {
        const int m = m0 + wm * 32 + mi * 16 + r;
#pragma unroll
        for (int ni = 0; ni < 8; ni++) {
            const int n = n0 + wn * 64 + ni * 8 + 2 * c;
            *reinterpret_cast<float2*>(out + (size_t)m * Dq + n) =
                make_float2(acc[mi][ni][0], acc[mi][ni][1]);
            *reinterpret_cast<float2*>(out + (size_t)(m + 8) * Dq + n) =
                make_float2(acc[mi][ni][2], acc[mi][ni][3]);
        }
    }
}

// ---------------------------------------------------------------------------
// Launch
// ---------------------------------------------------------------------------
extern "C" void kernel_launch(void* const* d_in, const int* in_sizes, int n_in,
                              void* d_out, int out_size)
{
    const float* x     = (const float*)d_in[0];
    const float* w_qkv = (const float*)d_in[1];
    const float* w_o   = (const float*)d_in[2];
    float* out = (float*)d_out;

    cudaFuncSetAttribute(k_flash, cudaFuncAttributeMaxDynamicSharedMemorySize, FLASH_SMEM);

    k_gemm_qkv<<<dim3(QKV_O / BN, MROWS / BM), NTHREADS>>>(x, w_qkv);
    k_rope<<<dim3(Sq, Bq), 256>>>();
    k_flash<<<dim3(16, Bq * NH), NTHREADS, FLASH_SMEM>>>();
    k_gemm_out<<<dim3(Dq / BN, MROWS / BM), NTHREADS>>>(w_o, out);
}